// round 4
// baseline (speedup 1.0000x reference)
#include <cuda_runtime.h>
#include <stdint.h>

#define BB 4
#define SS 2048
#define DD 1024
#define EE 64
#define CC 64
#define ROWS (BB*SS)          // 8192
#define NOISE_SCALE (1.0f/64.0f)
#define HALF ((size_t)BB*SS*EE*CC)      // elements per output array
#define TOTAL_F4 ((2*HALF)/4)           // float4 count of full output (16,777,216)

#define GEMM_BLOCKS 128
#define ZERO_BLOCKS 464
#define FAT_GRID    (GEMM_BLOCKS + ZERO_BLOCKS)   // 592 = 4 * 148

// Scratch: gates transposed [b][e][s]  (2 MB)
__device__ float g_gatesT[(size_t)BB*EE*SS];

// ---------------------------------------------------------------------------
// Fat kernel: blocks 0..127 do the GEMM+softmax; blocks 128..591 zero-fill the
// 268MB output. 48KB smem/block -> exactly 4 blocks/SM -> all 592 blocks are
// resident in ONE wave, so DRAM fill and FMA compute overlap by construction.
// ---------------------------------------------------------------------------
__global__ __launch_bounds__(256, 4)
void fused_gemm_zero_kernel(const float* __restrict__ X,
                            const float* __restrict__ W,
                            const float* __restrict__ noise,
                            float4* __restrict__ out4)
{
    __shared__ float As[64][66];   // [row][k]
    __shared__ float Ws[64][64];   // [k][expert]; reused for logits in epilogue

    const int tid = threadIdx.x;

    if (blockIdx.x >= GEMM_BLOCKS) {
        // ---- zero path: coalesced grid-stride float4 fill ----
        const float4 z = make_float4(0.f, 0.f, 0.f, 0.f);
        const size_t stride = (size_t)ZERO_BLOCKS * 256;
        for (size_t i = (size_t)(blockIdx.x - GEMM_BLOCKS) * 256 + tid;
             i < TOTAL_F4; i += stride)
            out4[i] = z;
        return;
    }

    // ---- gemm path ----
    const int tx   = tid & 15;     // expert group (4 experts)
    const int ty   = tid >> 4;     // row group (4 rows)
    const int row0 = blockIdx.x * 64;

    float acc[4][4];
#pragma unroll
    for (int i = 0; i < 4; i++)
#pragma unroll
        for (int j = 0; j < 4; j++) acc[i][j] = 0.0f;

    for (int k0 = 0; k0 < DD; k0 += 64) {
#pragma unroll
        for (int p = 0; p < 4; p++) {
            int r  = (tid >> 4) + p * 16;
            int kv = (tid & 15) * 4;
            float4 v = *(const float4*)&X[(size_t)(row0 + r) * DD + k0 + kv];
            As[r][kv + 0] = v.x;
            As[r][kv + 1] = v.y;
            As[r][kv + 2] = v.z;
            As[r][kv + 3] = v.w;
        }
#pragma unroll
        for (int p = 0; p < 4; p++) {
            int kk = (tid >> 4) + p * 16;
            int ev = (tid & 15) * 4;
            *(float4*)&Ws[kk][ev] = *(const float4*)&W[(size_t)(k0 + kk) * EE + ev];
        }
        __syncthreads();

#pragma unroll
        for (int kk = 0; kk < 64; kk += 2) {
            float4 b0 = *(const float4*)&Ws[kk + 0][tx * 4];
            float4 b1 = *(const float4*)&Ws[kk + 1][tx * 4];
#pragma unroll
            for (int i = 0; i < 4; i++) {
                float2 a = *(const float2*)&As[ty * 4 + i][kk];
                acc[i][0] += a.x * b0.x; acc[i][1] += a.x * b0.y;
                acc[i][2] += a.x * b0.z; acc[i][3] += a.x * b0.w;
                acc[i][0] += a.y * b1.x; acc[i][1] += a.y * b1.y;
                acc[i][2] += a.y * b1.z; acc[i][3] += a.y * b1.w;
            }
        }
        __syncthreads();
    }

    // Epilogue: logits + noise into Ws (reused as [row][expert])
#pragma unroll
    for (int i = 0; i < 4; i++) {
        int r   = ty * 4 + i;
        int row = row0 + r;
#pragma unroll
        for (int j = 0; j < 4; j++) {
            int e = tx * 4 + j;
            Ws[r][e] = acc[i][j] + noise[(size_t)row * EE + e] * NOISE_SCALE;
        }
    }
    __syncthreads();

    // Softmax per row (threads 0..63), write transposed gates.
    if (tid < 64) {
        int r   = tid;
        int row = row0 + r;
        int b   = row / SS;
        int s   = row % SS;
        float m = -1e30f;
#pragma unroll
        for (int e = 0; e < EE; e++) m = fmaxf(m, Ws[r][e]);
        float sum = 0.0f;
#pragma unroll
        for (int e = 0; e < EE; e++) {
            float t = expf(Ws[r][e] - m);
            Ws[r][e] = t;
            sum += t;
        }
        float inv = 1.0f / sum;
#pragma unroll
        for (int e = 0; e < EE; e++) {
            g_gatesT[((size_t)b * EE + e) * SS + s] = Ws[r][e] * inv;
        }
    }
}

// ---------------------------------------------------------------------------
// Kernel 2: per-(b,e) exact top-64 via MSD radix select on u64 keys
// (gate_bits<<32)|~idx (distinct), then bitonic sort of <=512 candidates for
// exact rank order, then scatter. Grid: 256 blocks, 512 threads.
// ---------------------------------------------------------------------------
__global__ __launch_bounds__(512, 2)
void topk_kernel(float* __restrict__ mask_out,
                 float* __restrict__ comb_out)
{
    __shared__ unsigned long long keys[SS];
    __shared__ unsigned long long cand[512];
    __shared__ int hist[256];
    __shared__ unsigned long long s_prefix, s_thresh;
    __shared__ int s_need, s_done, s_cnt;

    const int tid = threadIdx.x;
    const int b = blockIdx.x >> 6;
    const int e = blockIdx.x & 63;

    const float* col = &g_gatesT[((size_t)b * EE + e) * SS];
    for (int i = tid; i < SS; i += 512) {
        unsigned int fb = __float_as_uint(col[i]);   // softmax gates >= 0
        keys[i] = ((unsigned long long)fb << 32) | (unsigned int)(~i);
    }
    if (tid == 0) { s_done = 0; s_need = CC; s_prefix = 0ULL; }
    __syncthreads();

    // MSD radix select, 8-bit digits. Exits when candidate set <= 512.
    for (int shift = 56; shift >= 0; shift -= 8) {
        if (s_done) break;
        if (tid < 256) hist[tid] = 0;
        __syncthreads();
        unsigned long long pf = s_prefix;
        for (int i = tid; i < SS; i += 512) {
            unsigned long long k = keys[i];
            bool active = (shift == 56) || ((k >> (shift + 8)) == pf);
            if (active) atomicAdd(&hist[(int)((k >> shift) & 255)], 1);
        }
        __syncthreads();
        if (tid == 0) {
            int need = s_need, c = 0, sel = 0;
            for (int d = 255; d >= 0; d--) {
                c += hist[d];
                if (c >= need) { sel = d; break; }
            }
            int above = c - hist[sel];
            int got = (CC - s_need) + c;            // keys >= boundary, globally
            unsigned long long np = (s_prefix << 8) | (unsigned long long)sel;
            if (got <= 512 || shift == 0) {
                s_thresh = np << shift;
                s_done = 1;
            } else {
                s_need = need - above;
                s_prefix = np;
            }
        }
        __syncthreads();
    }

    // Collect candidates (>= threshold), pad to 512 with 0 (real keys > 0).
    if (tid < 512) cand[tid] = 0ULL;
    if (tid == 0) s_cnt = 0;
    __syncthreads();
    {
        unsigned long long T = s_thresh;
        for (int i = tid; i < SS; i += 512) {
            unsigned long long k = keys[i];
            if (k >= T) { int p = atomicAdd(&s_cnt, 1); if (p < 512) cand[p] = k; }
        }
    }
    __syncthreads();

    // Bitonic sort 512 keys descending (exact ranks for the top 64).
    for (int k2 = 2; k2 <= 512; k2 <<= 1) {
        for (int j = k2 >> 1; j > 0; j >>= 1) {
            if (tid < 256) {
                int i   = ((tid & ~(j - 1)) << 1) | (tid & (j - 1));
                int ixj = i | j;
                bool desc = ((i & k2) == 0);
                unsigned long long a = cand[i];
                unsigned long long c = cand[ixj];
                if ((a < c) == desc) { cand[i] = c; cand[ixj] = a; }
            }
            __syncthreads();
        }
    }

    // Scatter top-64 (rank = c)
    if (tid < CC) {
        unsigned long long k = cand[tid];
        int   s = (int)(~(unsigned int)k);
        float v = __uint_as_float((unsigned int)(k >> 32));
        size_t idx = ((((size_t)b * SS + s) * EE + e) << 6) + tid;
        mask_out[idx] = 1.0f;
        comb_out[idx] = v;
    }
}

// ---------------------------------------------------------------------------
extern "C" void kernel_launch(void* const* d_in, const int* in_sizes, int n_in,
                              void* d_out, int out_size)
{
    const float* X     = (const float*)d_in[0];   // [B,S,D]
    const float* W     = (const float*)d_in[1];   // [D,E]
    const float* noise = (const float*)d_in[2];   // [B,S,E]
    float* out = (float*)d_out;

    fused_gemm_zero_kernel<<<FAT_GRID, 256>>>(X, W, noise, (float4*)out);
    topk_kernel<<<BB * EE, 512>>>(out, out + HALF);
}